// round 11
// baseline (speedup 1.0000x reference)
#include <cuda_runtime.h>
#include <math.h>

#define NB 4
#define KB 2
#define DB 2
#define KI 6
#define DI 5
#define ACCB (KB*(DB+1))   /* 6  */
#define ACCI (KI*(DI+1))   /* 36 */
#define TWO_DELTA_D 6.0f
#define DELTA_V 0.5f
#define PARAM_REG 0.001f

// ---------------- device scratch (no allocation allowed) --------------------
__device__ float g_bin_acc [NB][ACCB];   // per batch: [k]{sum_d..., count}
__device__ float g_inst_acc[NB][ACCI];
__device__ float g_bin_var [NB][KB];
__device__ float g_inst_var[NB][KI];
__device__ int   g_is64[2];
__device__ unsigned g_cnt;

__device__ __forceinline__ float f4c(const float4& v, int p) {
    return p == 0 ? v.x : (p == 1 ? v.y : (p == 2 ? v.z : v.w));
}

// ---------------- kernel 0: zero scratch + PARALLEL dtype detect ------------
__global__ void init_kernel(const int* __restrict__ binlab,
                            const int* __restrict__ instlab) {
    __shared__ int nz[2];
    int t = threadIdx.x;
    if (t == 0) { nz[0] = 0; nz[1] = 0; }
    float* pb = &g_bin_acc[0][0];
    for (int j = t; j < NB*ACCB; j += blockDim.x) pb[j] = 0.f;
    float* pi = &g_inst_acc[0][0];
    for (int j = t; j < NB*ACCI; j += blockDim.x) pi[j] = 0.f;
    float* vb = &g_bin_var[0][0];
    for (int j = t; j < NB*KB; j += blockDim.x) vb[j] = 0.f;
    float* vi = &g_inst_var[0][0];
    for (int j = t; j < NB*KI; j += blockDim.x) vi[j] = 0.f;
    __syncthreads();
    // int64 little-endian => odd 32-bit words of first 64 elems all zero.
    // int32 random labels => P(all zero) <= 2^-64. 64 parallel probes.
    if (t < 64) {
        if (binlab [2*t + 1] != 0) atomicOr(&nz[0], 1);
        if (instlab[2*t + 1] != 0) atomicOr(&nz[1], 1);
    }
    __syncthreads();
    if (t == 0) {
        g_is64[0] = nz[0] ? 0 : 1;
        g_is64[1] = nz[1] ? 0 : 1;
        g_cnt = 0u;
    }
}

// accumulate 4 pixels into acc[K*(D+1)]
template<int K, int D>
__device__ __forceinline__ void acc4(float* acc, const float4* x, const int* lab) {
#pragma unroll
    for (int p = 0; p < 4; p++) {
#pragma unroll
        for (int k = 0; k < K; k++) {
            float m = (lab[p] == k) ? 1.0f : 0.0f;
#pragma unroll
            for (int d = 0; d < D; d++)
                acc[k*(D+1)+d] = fmaf(m, f4c(x[d], p), acc[k*(D+1)+d]);
            acc[k*(D+1)+D] += m;
        }
    }
}

// ---------------- pass 1: sums + counts; 2 hoisted groups per thread --------
template<int K, int D>
__global__ __launch_bounds__(256)
void pass1_kernel(const float* __restrict__ logits,
                  const void*  __restrict__ labels,
                  float* __restrict__ gacc,     // [NB][K*(D+1)]
                  int labsel, int MN) {
    constexpr int ACC = K*(D+1);
    const int b = blockIdx.y;
    const float* base = logits + (size_t)b * D * MN;
    const int is64 = g_is64[labsel];
    const int nvec = MN >> 2;
    const int half = nvec >> 1;
    const size_t lv = (size_t)b * nvec;

    float acc[ACC];
#pragma unroll
    for (int j = 0; j < ACC; j++) acc[j] = 0.f;

    const int t = blockIdx.x*blockDim.x + threadIdx.x;
    if (t < half) {
        const int i0 = t, i1 = t + half;
        // -------- hoist ALL loads (12 independent LDGs) --------
        float4 x0[D], x1[D];
#pragma unroll
        for (int d = 0; d < D; d++) {
            const float4* s = (const float4*)(base + (size_t)d*MN);
            x0[d] = s[i0];
            x1[d] = s[i1];
        }
        int lab0[4], lab1[4];
        if (is64) {
            const longlong4 v0 = ((const longlong4*)labels)[lv + i0];
            const longlong4 v1 = ((const longlong4*)labels)[lv + i1];
            lab0[0]=(int)v0.x; lab0[1]=(int)v0.y; lab0[2]=(int)v0.z; lab0[3]=(int)v0.w;
            lab1[0]=(int)v1.x; lab1[1]=(int)v1.y; lab1[2]=(int)v1.z; lab1[3]=(int)v1.w;
        } else {
            const int4 v0 = ((const int4*)labels)[lv + i0];
            const int4 v1 = ((const int4*)labels)[lv + i1];
            lab0[0]=v0.x; lab0[1]=v0.y; lab0[2]=v0.z; lab0[3]=v0.w;
            lab1[0]=v1.x; lab1[1]=v1.y; lab1[2]=v1.z; lab1[3]=v1.w;
        }
        acc4<K,D>(acc, x0, lab0);
        acc4<K,D>(acc, x1, lab1);
        // odd remainder (nvec not divisible by 2*stride): handled generically
    }
    // generic tail for any leftover vectors beyond 2*half coverage
    for (int i = 2*half + t; i < nvec; i += gridDim.x*blockDim.x) {
        float4 x[D];
#pragma unroll
        for (int d = 0; d < D; d++)
            x[d] = ((const float4*)(base + (size_t)d*MN))[i];
        int lab[4];
        if (is64) {
            const longlong4 v = ((const longlong4*)labels)[lv + i];
            lab[0]=(int)v.x; lab[1]=(int)v.y; lab[2]=(int)v.z; lab[3]=(int)v.w;
        } else {
            const int4 v = ((const int4*)labels)[lv + i];
            lab[0]=v.x; lab[1]=v.y; lab[2]=v.z; lab[3]=v.w;
        }
        acc4<K,D>(acc, x, lab);
    }

#pragma unroll
    for (int j = 0; j < ACC; j++) {
        float v = acc[j];
#pragma unroll
        for (int o = 16; o; o >>= 1) v += __shfl_xor_sync(0xffffffffu, v, o);
        acc[j] = v;
    }
    __shared__ float red[ACC];
    if (threadIdx.x < ACC) red[threadIdx.x] = 0.f;
    __syncthreads();
    if ((threadIdx.x & 31) == 0) {
#pragma unroll
        for (int j = 0; j < ACC; j++) atomicAdd(&red[j], acc[j]);
    }
    __syncthreads();
    if (threadIdx.x < ACC) atomicAdd(&gacc[b*ACC + threadIdx.x], red[threadIdx.x]);
}

// push + reg terms from a [K*D] mean array
template<int K, int D>
__device__ __forceinline__ float rest_terms(const float* mean) {
    float ld = 0.f;
    for (int i = 0; i < K; i++)
        for (int j = 0; j < K; j++) if (i != j) {
            float s = 0.f;
            for (int d = 0; d < D; d++) {
                float df = mean[i*D+d] - mean[j*D+d];
                s += df*df;
            }
            float dn = fmaxf(TWO_DELTA_D - sqrtf(s), 0.f);
            ld += dn*dn;
        }
    ld /= (float)(K*(K-1));
    float lr = 0.f;
    for (int k = 0; k < K; k++) {
        float s = 0.f;
        for (int d = 0; d < D; d++) s += mean[k*D+d]*mean[k*D+d];
        lr += sqrtf(s);
    }
    lr /= (float)K;
    return ld + PARAM_REG * lr;
}

// final combine, run by the globally-last pass-2 CTA (thread 0)
__device__ void final_combine(float* __restrict__ out) {
    float bl = 0.f, il = 0.f;
    for (int bb = 0; bb < NB; bb++) {
        float mb[KB*DB], mi[KI*DI];
        float lvv = 0.f;
        for (int k = 0; k < KB; k++) {
            float c = __ldcg(&g_bin_acc[bb][k*(DB+1)+DB]);
            for (int d = 0; d < DB; d++)
                mb[k*DB+d] = __ldcg(&g_bin_acc[bb][k*(DB+1)+d]) / c;
            lvv += __ldcg(&g_bin_var[bb][k]) / c;
        }
        bl += lvv / (float)KB + rest_terms<KB,DB>(mb);
        float lvi = 0.f;
        for (int k = 0; k < KI; k++) {
            float c = __ldcg(&g_inst_acc[bb][k*(DI+1)+DI]);
            for (int d = 0; d < DI; d++)
                mi[k*DI+d] = __ldcg(&g_inst_acc[bb][k*(DI+1)+d]) / c;
            lvi += __ldcg(&g_inst_var[bb][k]) / c;
        }
        il += lvi / (float)KI + rest_terms<KI,DI>(mi);
    }
    out[0] = bl / (float)NB;
    out[1] = il / (float)NB;
}

// hinge accumulate 4 pixels
template<int K, int D>
__device__ __forceinline__ void hinge4(float* accv, const float (*mean)[D],
                                       const float4* x, const int* lab) {
#pragma unroll
    for (int p = 0; p < 4; p++) {
        float m[K];
#pragma unroll
        for (int k = 0; k < K; k++) m[k] = (lab[p] == k) ? 1.0f : 0.0f;
        float dist2 = 0.f;
#pragma unroll
        for (int d = 0; d < D; d++) {
            float mu = 0.f;
#pragma unroll
            for (int k = 0; k < K; k++) mu = fmaf(m[k], mean[k][d], mu);
            float tdf = f4c(x[d], p) - mu;
            dist2 = fmaf(tdf, tdf, dist2);
        }
        float h  = fmaxf(sqrtf(dist2) - DELTA_V, 0.f);
        float h2 = h*h;
#pragma unroll
        for (int k = 0; k < K; k++) accv[k] = fmaf(m[k], h2, accv[k]);
    }
}

// ---------------- pass 2: hinge variance; smem means; 2 hoisted groups ------
template<int K, int D>
__global__ __launch_bounds__(256)
void pass2_kernel(const float* __restrict__ logits,
                  const void*  __restrict__ labels,
                  const float* __restrict__ gacc,    // [NB][K*(D+1)]
                  float* __restrict__ gvar,          // [NB][K]
                  float* __restrict__ out,
                  unsigned total_ctas,
                  int labsel, int MN) {
    const int b = blockIdx.y;
    const float* base = logits + (size_t)b * D * MN;
    const int is64 = g_is64[labsel];
    const int nvec = MN >> 2;
    const int half = nvec >> 1;
    const size_t lv = (size_t)b * nvec;

    // means computed ONCE per CTA (K*D loads + divides total, not per thread)
    __shared__ float smean[K*D];
    if (threadIdx.x < K*D) {
        int k = threadIdx.x / D, d = threadIdx.x % D;
        smean[threadIdx.x] = gacc[b*K*(D+1) + k*(D+1)+d]
                           / gacc[b*K*(D+1) + k*(D+1)+D];
    }
    __syncthreads();
    float mean[K][D];
#pragma unroll
    for (int k = 0; k < K; k++)
#pragma unroll
        for (int d = 0; d < D; d++)
            mean[k][d] = smean[k*D+d];

    float accv[K];
#pragma unroll
    for (int k = 0; k < K; k++) accv[k] = 0.f;

    const int t = blockIdx.x*blockDim.x + threadIdx.x;
    if (t < half) {
        const int i0 = t, i1 = t + half;
        float4 x0[D], x1[D];
#pragma unroll
        for (int d = 0; d < D; d++) {
            const float4* s = (const float4*)(base + (size_t)d*MN);
            x0[d] = s[i0];
            x1[d] = s[i1];
        }
        int lab0[4], lab1[4];
        if (is64) {
            const longlong4 v0 = ((const longlong4*)labels)[lv + i0];
            const longlong4 v1 = ((const longlong4*)labels)[lv + i1];
            lab0[0]=(int)v0.x; lab0[1]=(int)v0.y; lab0[2]=(int)v0.z; lab0[3]=(int)v0.w;
            lab1[0]=(int)v1.x; lab1[1]=(int)v1.y; lab1[2]=(int)v1.z; lab1[3]=(int)v1.w;
        } else {
            const int4 v0 = ((const int4*)labels)[lv + i0];
            const int4 v1 = ((const int4*)labels)[lv + i1];
            lab0[0]=v0.x; lab0[1]=v0.y; lab0[2]=v0.z; lab0[3]=v0.w;
            lab1[0]=v1.x; lab1[1]=v1.y; lab1[2]=v1.z; lab1[3]=v1.w;
        }
        hinge4<K,D>(accv, mean, x0, lab0);
        hinge4<K,D>(accv, mean, x1, lab1);
    }
    for (int i = 2*half + t; i < nvec; i += gridDim.x*blockDim.x) {
        float4 x[D];
#pragma unroll
        for (int d = 0; d < D; d++)
            x[d] = ((const float4*)(base + (size_t)d*MN))[i];
        int lab[4];
        if (is64) {
            const longlong4 v = ((const longlong4*)labels)[lv + i];
            lab[0]=(int)v.x; lab[1]=(int)v.y; lab[2]=(int)v.z; lab[3]=(int)v.w;
        } else {
            const int4 v = ((const int4*)labels)[lv + i];
            lab[0]=v.x; lab[1]=v.y; lab[2]=v.z; lab[3]=v.w;
        }
        hinge4<K,D>(accv, mean, x, lab);
    }

#pragma unroll
    for (int k = 0; k < K; k++) {
        float v = accv[k];
#pragma unroll
        for (int o = 16; o; o >>= 1) v += __shfl_xor_sync(0xffffffffu, v, o);
        accv[k] = v;
    }
    __shared__ float red[K];
    if (threadIdx.x < K) red[threadIdx.x] = 0.f;
    __syncthreads();
    if ((threadIdx.x & 31) == 0) {
#pragma unroll
        for (int k = 0; k < K; k++) atomicAdd(&red[k], accv[k]);
    }
    __syncthreads();
    if (threadIdx.x < K) atomicAdd(&gvar[b*K + threadIdx.x], red[threadIdx.x]);
    __syncthreads();

    // global completion counter across BOTH pass-2 kernels
    if (threadIdx.x == 0) {
        __threadfence();
        unsigned p = atomicAdd(&g_cnt, 1u);
        if (p == total_ctas - 1u) {
            __threadfence();
            final_combine(out);
        }
    }
}

// ---------------- launch -----------------------------------------------------
extern "C" void kernel_launch(void* const* d_in, const int* in_sizes, int n_in,
                              void* d_out, int out_size) {
    const float* bin_logits  = (const float*)d_in[0];
    const void*  bin_labels  = d_in[1];
    const float* inst_logits = (const float*)d_in[2];
    const void*  inst_labels = d_in[3];
    float* out = (float*)d_out;

    const int MN   = in_sizes[1] / NB;
    const int nvec = MN >> 2;
    const int half = nvec >> 1;
    const int GXp  = (half + 255) / 256;   // one thread per (i, i+half) pair

    float *p_bin_acc, *p_inst_acc, *p_bin_var, *p_inst_var;
    cudaGetSymbolAddress((void**)&p_bin_acc,  g_bin_acc);
    cudaGetSymbolAddress((void**)&p_inst_acc, g_inst_acc);
    cudaGetSymbolAddress((void**)&p_bin_var,  g_bin_var);
    cudaGetSymbolAddress((void**)&p_inst_var, g_inst_var);

    dim3 grid(GXp, NB);
    const unsigned total_ctas = 2u * GXp * NB;   // both pass-2 kernels combined

    init_kernel<<<1, 256>>>((const int*)bin_labels, (const int*)inst_labels);
    pass1_kernel<KB, DB><<<grid, 256>>>(bin_logits,  bin_labels,  p_bin_acc,  0, MN);
    pass1_kernel<KI, DI><<<grid, 256>>>(inst_logits, inst_labels, p_inst_acc, 1, MN);
    pass2_kernel<KB, DB><<<grid, 256>>>(bin_logits,  bin_labels,  p_bin_acc,  p_bin_var,  out, total_ctas, 0, MN);
    pass2_kernel<KI, DI><<<grid, 256>>>(inst_logits, inst_labels, p_inst_acc, p_inst_var, out, total_ctas, 1, MN);
}

// round 12
// speedup vs baseline: 1.9699x; 1.9699x over previous
#include <cuda_runtime.h>
#include <math.h>

#define NB 4
#define KB 2
#define DB 2
#define KI 6
#define DI 5
#define ACCB (KB*(DB+1))   /* 6  */
#define ACCI (KI*(DI+1))   /* 36 */
#define TWO_DELTA_D 6.0f
#define DELTA_V 0.5f
#define PARAM_REG 0.001f
#define MAXLAB (4*512*1024)    /* uint8 packed labels per task */
#define GX 256

// ---------------- device scratch (no allocation allowed) --------------------
__device__ float g_bin_acc [NB][ACCB];   // per batch: [k]{sum_d..., count}
__device__ float g_inst_acc[NB][ACCI];
__device__ float g_bin_var [NB][KB];
__device__ float g_inst_var[NB][KI];
__device__ int   g_is64[2];
__device__ unsigned char g_plab_bin [MAXLAB];
__device__ unsigned char g_plab_inst[MAXLAB];

__device__ __forceinline__ float f4c(const float4& v, int p) {
    return p == 0 ? v.x : (p == 1 ? v.y : (p == 2 ? v.z : v.w));
}

// ---------------- kernel 0: zero scratch + PARALLEL dtype detect ------------
__global__ void init_kernel(const int* __restrict__ binlab,
                            const int* __restrict__ instlab) {
    __shared__ int nz[2];
    int t = threadIdx.x;
    if (t == 0) { nz[0] = 0; nz[1] = 0; }
    float* pb = &g_bin_acc[0][0];
    for (int j = t; j < NB*ACCB; j += blockDim.x) pb[j] = 0.f;
    float* pi = &g_inst_acc[0][0];
    for (int j = t; j < NB*ACCI; j += blockDim.x) pi[j] = 0.f;
    float* vb = &g_bin_var[0][0];
    for (int j = t; j < NB*KB; j += blockDim.x) vb[j] = 0.f;
    float* vi = &g_inst_var[0][0];
    for (int j = t; j < NB*KI; j += blockDim.x) vi[j] = 0.f;
    __syncthreads();
    // int64 little-endian => odd 32-bit words of first 64 elems all zero.
    // int32 random labels => P(all zero) <= 2^-64. 64 parallel probes.
    if (t < 64) {
        if (binlab [2*t + 1] != 0) atomicOr(&nz[0], 1);
        if (instlab[2*t + 1] != 0) atomicOr(&nz[1], 1);
    }
    __syncthreads();
    if (t == 0) {
        g_is64[0] = nz[0] ? 0 : 1;
        g_is64[1] = nz[1] ? 0 : 1;
    }
}

// ---------------- pass 1: sums + counts + label packing ---------------------
template<int K, int D>
__global__ __launch_bounds__(256)
void pass1_kernel(const float* __restrict__ logits,
                  const void*  __restrict__ labels,
                  unsigned char* __restrict__ plab,
                  float* __restrict__ gacc,     // [NB][K*(D+1)]
                  int labsel, int MN, int pack) {
    constexpr int ACC = K*(D+1);
    const int b = blockIdx.y;
    const float* base = logits + (size_t)b * D * MN;
    const int is64 = g_is64[labsel];
    const int nvec = MN >> 2;
    const size_t lv = (size_t)b * nvec;

    float acc[ACC];
#pragma unroll
    for (int j = 0; j < ACC; j++) acc[j] = 0.f;

    for (int i = blockIdx.x*blockDim.x + threadIdx.x; i < nvec;
         i += gridDim.x*blockDim.x) {
        float4 x[D];
#pragma unroll
        for (int d = 0; d < D; d++)
            x[d] = ((const float4*)(base + (size_t)d*MN))[i];
        int lab[4];
        if (is64) {
            const longlong4 v = ((const longlong4*)labels)[lv + i];
            lab[0]=(int)v.x; lab[1]=(int)v.y; lab[2]=(int)v.z; lab[3]=(int)v.w;
        } else {
            const int4 v = ((const int4*)labels)[lv + i];
            lab[0]=v.x; lab[1]=v.y; lab[2]=v.z; lab[3]=v.w;
        }
        if (pack) {
            uchar4 pc;
            pc.x = (unsigned char)lab[0]; pc.y = (unsigned char)lab[1];
            pc.z = (unsigned char)lab[2]; pc.w = (unsigned char)lab[3];
            ((uchar4*)plab)[lv + i] = pc;
        }
#pragma unroll
        for (int p = 0; p < 4; p++) {
#pragma unroll
            for (int k = 0; k < K; k++) {
                float m = (lab[p] == k) ? 1.0f : 0.0f;
#pragma unroll
                for (int d = 0; d < D; d++)
                    acc[k*(D+1)+d] = fmaf(m, f4c(x[d], p), acc[k*(D+1)+d]);
                acc[k*(D+1)+D] += m;
            }
        }
    }

#pragma unroll
    for (int j = 0; j < ACC; j++) {
        float v = acc[j];
#pragma unroll
        for (int o = 16; o; o >>= 1) v += __shfl_xor_sync(0xffffffffu, v, o);
        acc[j] = v;
    }
    __shared__ float red[ACC];
    if (threadIdx.x < ACC) red[threadIdx.x] = 0.f;
    __syncthreads();
    if ((threadIdx.x & 31) == 0) {
#pragma unroll
        for (int j = 0; j < ACC; j++) atomicAdd(&red[j], acc[j]);
    }
    __syncthreads();
    if (threadIdx.x < ACC) atomicAdd(&gacc[b*ACC + threadIdx.x], red[threadIdx.x]);
}

// ---------------- pass 2: hinge variance; smem means; packed labels ---------
template<int K, int D>
__global__ __launch_bounds__(256)
void pass2_kernel(const float* __restrict__ logits,
                  const unsigned char* __restrict__ plab,
                  const void* __restrict__ labels,   // fallback if !pack
                  const float* __restrict__ gacc,    // [NB][K*(D+1)]
                  float* __restrict__ gvar,          // [NB][K]
                  int labsel, int MN, int pack) {
    const int b = blockIdx.y;
    const float* base = logits + (size_t)b * D * MN;
    const int nvec = MN >> 2;
    const size_t lv = (size_t)b * nvec;
    const int is64 = g_is64[labsel];

    // means computed ONCE per CTA
    __shared__ float smean[K*D];
    if (threadIdx.x < K*D) {
        int k = threadIdx.x / D, d = threadIdx.x % D;
        smean[threadIdx.x] = gacc[b*K*(D+1) + k*(D+1)+d]
                           / gacc[b*K*(D+1) + k*(D+1)+D];
    }
    __syncthreads();

    float accv[K];
#pragma unroll
    for (int k = 0; k < K; k++) accv[k] = 0.f;

    for (int i = blockIdx.x*blockDim.x + threadIdx.x; i < nvec;
         i += gridDim.x*blockDim.x) {
        float4 x[D];
#pragma unroll
        for (int d = 0; d < D; d++)
            x[d] = ((const float4*)(base + (size_t)d*MN))[i];
        int lab[4];
        if (pack) {
            const uchar4 pc = ((const uchar4*)plab)[lv + i];
            lab[0]=pc.x; lab[1]=pc.y; lab[2]=pc.z; lab[3]=pc.w;
        } else if (is64) {
            const longlong4 v = ((const longlong4*)labels)[lv + i];
            lab[0]=(int)v.x; lab[1]=(int)v.y; lab[2]=(int)v.z; lab[3]=(int)v.w;
        } else {
            const int4 v = ((const int4*)labels)[lv + i];
            lab[0]=v.x; lab[1]=v.y; lab[2]=v.z; lab[3]=v.w;
        }
#pragma unroll
        for (int p = 0; p < 4; p++) {
            const float* mu = smean + lab[p]*D;
            float dist2 = 0.f;
#pragma unroll
            for (int d = 0; d < D; d++) {
                float df = f4c(x[d], p) - mu[d];
                dist2 = fmaf(df, df, dist2);
            }
            float h  = fmaxf(sqrtf(dist2) - DELTA_V, 0.f);
            float h2 = h*h;
#pragma unroll
            for (int k = 0; k < K; k++)
                accv[k] += (lab[p] == k) ? h2 : 0.f;
        }
    }

#pragma unroll
    for (int k = 0; k < K; k++) {
        float v = accv[k];
#pragma unroll
        for (int o = 16; o; o >>= 1) v += __shfl_xor_sync(0xffffffffu, v, o);
        accv[k] = v;
    }
    __shared__ float red[K];
    if (threadIdx.x < K) red[threadIdx.x] = 0.f;
    __syncthreads();
    if ((threadIdx.x & 31) == 0) {
#pragma unroll
        for (int k = 0; k < K; k++) atomicAdd(&red[k], accv[k]);
    }
    __syncthreads();
    if (threadIdx.x < K) atomicAdd(&gvar[b*K + threadIdx.x], red[threadIdx.x]);
}

// ---------------- final kernel: parallel combine ----------------------------
__global__ void final_kernel(float* __restrict__ out) {
    __shared__ float sba[NB*ACCB];
    __shared__ float sia[NB*ACCI];
    __shared__ float sbv[NB*KB];
    __shared__ float siv[NB*KI];
    __shared__ float smb[NB*KB*DB];
    __shared__ float smi[NB*KI*DI];
    __shared__ float s_ld_b[NB], s_ld_i[NB];
    __shared__ float s_lr_b[NB], s_lr_i[NB];
    __shared__ float s_lv_b[NB], s_lv_i[NB];
    const int t = threadIdx.x;

    for (int j = t; j < NB*ACCB; j += blockDim.x) sba[j] = (&g_bin_acc [0][0])[j];
    for (int j = t; j < NB*ACCI; j += blockDim.x) sia[j] = (&g_inst_acc[0][0])[j];
    for (int j = t; j < NB*KB;   j += blockDim.x) sbv[j] = (&g_bin_var [0][0])[j];
    for (int j = t; j < NB*KI;   j += blockDim.x) siv[j] = (&g_inst_var[0][0])[j];
    if (t < 2*NB) {
        int i = t;
        if (i < NB) { s_ld_b[i]=0.f; s_lr_b[i]=0.f; s_lv_b[i]=0.f; }
        else { i -= NB; s_ld_i[i]=0.f; s_lr_i[i]=0.f; s_lv_i[i]=0.f; }
    }
    __syncthreads();

    for (int j = t; j < NB*KB*DB; j += blockDim.x) {
        int bb = j / (KB*DB), r = j % (KB*DB), k = r / DB, d = r % DB;
        smb[j] = sba[bb*ACCB + k*(DB+1)+d] / sba[bb*ACCB + k*(DB+1)+DB];
    }
    for (int j = t; j < NB*KI*DI; j += blockDim.x) {
        int bb = j / (KI*DI), r = j % (KI*DI), k = r / DI, d = r % DI;
        smi[j] = sia[bb*ACCI + k*(DI+1)+d] / sia[bb*ACCI + k*(DI+1)+DI];
    }
    __syncthreads();

    for (int j = t; j < NB*KB; j += blockDim.x) {
        int bb = j / KB, k = j % KB;
        atomicAdd(&s_lv_b[bb], sbv[j] / sba[bb*ACCB + k*(DB+1)+DB]);
    }
    for (int j = t; j < NB*KI; j += blockDim.x) {
        int bb = j / KI, k = j % KI;
        atomicAdd(&s_lv_i[bb], siv[j] / sia[bb*ACCI + k*(DI+1)+DI]);
    }
    for (int j = t; j < NB*KB*KB; j += blockDim.x) {
        int bb = j / (KB*KB), r = j % (KB*KB), i = r / KB, jj = r % KB;
        if (i != jj) {
            float s = 0.f;
            for (int d = 0; d < DB; d++) {
                float df = smb[bb*KB*DB + i*DB+d] - smb[bb*KB*DB + jj*DB+d];
                s += df*df;
            }
            float dn = fmaxf(TWO_DELTA_D - sqrtf(s), 0.f);
            atomicAdd(&s_ld_b[bb], dn*dn);
        }
    }
    for (int j = t; j < NB*KI*KI; j += blockDim.x) {
        int bb = j / (KI*KI), r = j % (KI*KI), i = r / KI, jj = r % KI;
        if (i != jj) {
            float s = 0.f;
            for (int d = 0; d < DI; d++) {
                float df = smi[bb*KI*DI + i*DI+d] - smi[bb*KI*DI + jj*DI+d];
                s += df*df;
            }
            float dn = fmaxf(TWO_DELTA_D - sqrtf(s), 0.f);
            atomicAdd(&s_ld_i[bb], dn*dn);
        }
    }
    for (int j = t; j < NB*KB; j += blockDim.x) {
        int bb = j / KB, k = j % KB;
        float s = 0.f;
        for (int d = 0; d < DB; d++) {
            float v = smb[bb*KB*DB + k*DB+d];
            s += v*v;
        }
        atomicAdd(&s_lr_b[bb], sqrtf(s));
    }
    for (int j = t; j < NB*KI; j += blockDim.x) {
        int bb = j / KI, k = j % KI;
        float s = 0.f;
        for (int d = 0; d < DI; d++) {
            float v = smi[bb*KI*DI + k*DI+d];
            s += v*v;
        }
        atomicAdd(&s_lr_i[bb], sqrtf(s));
    }
    __syncthreads();

    if (t == 0) {
        float bl = 0.f, il = 0.f;
        for (int bb = 0; bb < NB; bb++) {
            bl += s_lv_b[bb] / (float)KB
                + s_ld_b[bb] / (float)(KB*(KB-1))
                + PARAM_REG * (s_lr_b[bb] / (float)KB);
            il += s_lv_i[bb] / (float)KI
                + s_ld_i[bb] / (float)(KI*(KI-1))
                + PARAM_REG * (s_lr_i[bb] / (float)KI);
        }
        out[0] = bl / (float)NB;
        out[1] = il / (float)NB;
    }
}

// ---------------- launch: fork/join multi-stream graph ----------------------
extern "C" void kernel_launch(void* const* d_in, const int* in_sizes, int n_in,
                              void* d_out, int out_size) {
    const float* bin_logits  = (const float*)d_in[0];
    const void*  bin_labels  = d_in[1];
    const float* inst_logits = (const float*)d_in[2];
    const void*  inst_labels = d_in[3];
    float* out = (float*)d_out;

    const int MN = in_sizes[1] / NB;
    const int pack = (in_sizes[1] <= MAXLAB) ? 1 : 0;

    float *p_bin_acc, *p_inst_acc, *p_bin_var, *p_inst_var;
    unsigned char *p_plab_bin, *p_plab_inst;
    cudaGetSymbolAddress((void**)&p_bin_acc,   g_bin_acc);
    cudaGetSymbolAddress((void**)&p_inst_acc,  g_inst_acc);
    cudaGetSymbolAddress((void**)&p_bin_var,   g_bin_var);
    cudaGetSymbolAddress((void**)&p_inst_var,  g_inst_var);
    cudaGetSymbolAddress((void**)&p_plab_bin,  g_plab_bin);
    cudaGetSymbolAddress((void**)&p_plab_inst, g_plab_inst);

    // streams/events memoized: created on the (uncaptured) correctness call;
    // graph replays never re-run host code, so this only shapes the graph.
    static cudaStream_t s1 = nullptr;
    static cudaEvent_t  e0 = nullptr, e1 = nullptr;
    if (s1 == nullptr) {
        cudaStreamCreateWithFlags(&s1, cudaStreamNonBlocking);
        cudaEventCreateWithFlags(&e0, cudaEventDisableTiming);
        cudaEventCreateWithFlags(&e1, cudaEventDisableTiming);
    }

    dim3 grid(GX, NB);

    init_kernel<<<1, 256>>>((const int*)bin_labels, (const int*)inst_labels);
    cudaEventRecord(e0, 0);
    cudaStreamWaitEvent(s1, e0, 0);
    // inst chain (104 MB) on s1, concurrent with bin chain below
    pass1_kernel<KI, DI><<<grid, 256, 0, s1>>>(inst_logits, inst_labels, p_plab_inst, p_inst_acc, 1, MN, pack);
    pass2_kernel<KI, DI><<<grid, 256, 0, s1>>>(inst_logits, p_plab_inst, inst_labels, p_inst_acc, p_inst_var, 1, MN, pack);
    cudaEventRecord(e1, s1);
    // bin chain (56 MB) on default stream
    pass1_kernel<KB, DB><<<grid, 256>>>(bin_logits, bin_labels, p_plab_bin, p_bin_acc, 0, MN, pack);
    pass2_kernel<KB, DB><<<grid, 256>>>(bin_logits, p_plab_bin, bin_labels, p_bin_acc, p_bin_var, 0, MN, pack);
    cudaStreamWaitEvent(0, e1, 0);
    final_kernel<<<1, 128>>>(out);
}